// round 12
// baseline (speedup 1.0000x reference)
#include <cuda_runtime.h>
#include <cstddef>
#include <cstdint>

#define BB 2
#define SEQ 4096
#define DMODEL 768
#define NHEADS 12
#define HDIM 64
#define MTOT (BB * SEQ)   // 8192
#define QKVS (3 * DMODEL) // 2304 fused qkv row stride

// Scratch (alloc-free rule: __device__ globals)
__device__ float g_xt[MTOT * DMODEL];            // x, tf32-rounded
__device__ float g_wt[4 * DMODEL * DMODEL];      // [0..3*D*D): wqkv interleaved [k][3n]; [3*D*D..): wo [k][n]
__device__ float g_qkv[MTOT * QKVS];             // fused q|k|v rows
__device__ float g_ctx[MTOT * DMODEL];

// single dynamic-smem symbol shared by all kernels
extern __shared__ unsigned dynsmem[];

// ---------------------------------------------------------------------------
// helpers
// ---------------------------------------------------------------------------
__device__ __forceinline__ unsigned f2tf(float f) {
    unsigned u;
    asm("cvt.rna.tf32.f32 %0, %1;" : "=r"(u) : "f"(f));
    return u;
}
__device__ __forceinline__ float ex2f(float x) {
    float y;
    asm("ex2.approx.f32 %0, %1;" : "=f"(y) : "f"(x));
    return y;
}
__device__ __forceinline__ void mma8(float c[4], const unsigned a[4], const unsigned b[2]) {
    asm volatile(
        "mma.sync.aligned.m16n8k8.row.col.f32.tf32.tf32.f32 "
        "{%0,%1,%2,%3}, {%4,%5,%6,%7}, {%8,%9}, {%0,%1,%2,%3};\n"
        : "+f"(c[0]), "+f"(c[1]), "+f"(c[2]), "+f"(c[3])
        : "r"(a[0]), "r"(a[1]), "r"(a[2]), "r"(a[3]), "r"(b[0]), "r"(b[1]));
}
__device__ __forceinline__ void cp16(uint32_t dst, const void* src) {
    asm volatile("cp.async.cg.shared.global [%0], [%1], 16;\n" :: "r"(dst), "l"(src));
}
#define CP_COMMIT() asm volatile("cp.async.commit_group;\n" ::: "memory")
#define CP_WAIT0()  asm volatile("cp.async.wait_group 0;\n" ::: "memory")

// ---------------------------------------------------------------------------
// prep kernels
// ---------------------------------------------------------------------------
__global__ void prep_tf32(const float* __restrict__ src, float* __restrict__ dst, int n4)
{
    int i = blockIdx.x * blockDim.x + threadIdx.x;
    if (i >= n4) return;
    float4 v = ((const float4*)src)[i];
    v.x = __uint_as_float(f2tf(v.x));
    v.y = __uint_as_float(f2tf(v.y));
    v.z = __uint_as_float(f2tf(v.z));
    v.w = __uint_as_float(f2tf(v.w));
    ((float4*)dst)[i] = v;
}

// Pack weights: mats 0..2 (wq,wk,wv) -> interleaved [k][mat*768+n] with qscale
// folded into wq; mat 3 (wo) -> linear at offset 3*D*D.
__global__ void prep_tf32_w(const float* __restrict__ w0, const float* __restrict__ w1,
                            const float* __restrict__ w2, const float* __restrict__ w3,
                            float* __restrict__ dst, int n4, float qscale)
{
    int i = blockIdx.x * blockDim.x + threadIdx.x;
    if (i >= n4) return;
    const int mat = blockIdx.y;
    const float* src = (mat == 0) ? w0 : (mat == 1) ? w1 : (mat == 2) ? w2 : w3;
    const float s = (mat == 0) ? qscale : 1.0f;
    float4 v = ((const float4*)src)[i];
    v.x = __uint_as_float(f2tf(v.x * s));
    v.y = __uint_as_float(f2tf(v.y * s));
    v.z = __uint_as_float(f2tf(v.z * s));
    v.w = __uint_as_float(f2tf(v.w * s));
    if (mat < 3) {
        int k = (i * 4) / DMODEL, n = (i * 4) % DMODEL;
        *(float4*)(dst + (size_t)k * QKVS + mat * DMODEL + n) = v;
    } else {
        ((float4*)(dst + (size_t)3 * DMODEL * DMODEL))[i] = v;
    }
}

// ---------------------------------------------------------------------------
// tf32 GEMM: C = A@B (+bias, optional tf32-round). 128 thr, CTA 128x64x32,
// 4 warps, warp tile 32x64. cp.async 2-stage. 4 CTAs/SM.
// ---------------------------------------------------------------------------
#define TBM 128
#define TBN 64
#define TBK 32
#define ASTR 36
#define BSTR 72
#define GBUF (TBM * ASTR + TBK * BSTR)   // 6912 words per stage
#define GEMM_SMEM (2 * GBUF * 4)         // 55296 B

__global__ __launch_bounds__(128, 4) void gemm_tf32(
    const float* __restrict__ A, const float* __restrict__ B,
    const float* __restrict__ bias, float* __restrict__ C,
    int M, int N, int K, int conv_out)
{
    unsigned* gsm = dynsmem;
    const uint32_t sbase = (uint32_t)__cvta_generic_to_shared(gsm);

    const int tid  = threadIdx.x;
    const int lane = tid & 31;
    const int w    = tid >> 5;       // 0..3
    const int g    = lane >> 2;
    const int t    = lane & 3;
    const int wm   = w * 32;
    const int row0 = blockIdx.y * TBM;
    const int col0 = blockIdx.x * TBN;

    float c[2][8][4];
#pragma unroll
    for (int mi = 0; mi < 2; mi++)
#pragma unroll
        for (int ni = 0; ni < 8; ni++)
#pragma unroll
            for (int r = 0; r < 4; r++) c[mi][ni][r] = 0.0f;

    const int nk = K / TBK;

    auto load_tile = [&](int k0, int buf) {
#pragma unroll
        for (int i = 0; i < 8; i++) {
            int id = tid + 128 * i, r = id >> 3, cc = id & 7;
            cp16(sbase + (uint32_t)(buf * GBUF + r * ASTR + cc * 4) * 4,
                 A + (size_t)(row0 + r) * K + k0 + cc * 4);
        }
#pragma unroll
        for (int i = 0; i < 4; i++) {
            int id = tid + 128 * i, r = id >> 4, cc = id & 15;
            cp16(sbase + (uint32_t)(buf * GBUF + TBM * ASTR + r * BSTR + cc * 4) * 4,
                 B + (size_t)(k0 + r) * N + col0 + cc * 4);
        }
    };

    load_tile(0, 0);
    CP_COMMIT();

    for (int kt = 0; kt < nk; kt++) {
        CP_WAIT0();
        __syncthreads();
        if (kt + 1 < nk) {
            load_tile((kt + 1) * TBK, (kt + 1) & 1);
            CP_COMMIT();
        }
        const unsigned* Asb = gsm + (kt & 1) * GBUF;
        const unsigned* Bsb = Asb + TBM * ASTR;
#pragma unroll
        for (int kp = 0; kp < 4; kp++) {
            unsigned af[2][4], bf[8][2];
#pragma unroll
            for (int mi = 0; mi < 2; mi++) {
                int r0 = (wm + mi * 16 + g) * ASTR + kp * 8 + t;
                int r1 = (wm + mi * 16 + g + 8) * ASTR + kp * 8 + t;
                af[mi][0] = Asb[r0];
                af[mi][1] = Asb[r1];
                af[mi][2] = Asb[r0 + 4];
                af[mi][3] = Asb[r1 + 4];
            }
#pragma unroll
            for (int ni = 0; ni < 8; ni++) {
                bf[ni][0] = Bsb[(kp * 8 + t) * BSTR + ni * 8 + g];
                bf[ni][1] = Bsb[(kp * 8 + t + 4) * BSTR + ni * 8 + g];
            }
#pragma unroll
            for (int mi = 0; mi < 2; mi++)
#pragma unroll
                for (int ni = 0; ni < 8; ni++)
                    mma8(c[mi][ni], af[mi], bf[ni]);
        }
        __syncthreads();
    }

#pragma unroll
    for (int ni = 0; ni < 8; ni++) {
        int col = col0 + ni * 8 + 2 * t;
        float2 bv = make_float2(0.0f, 0.0f);
        if (bias) bv = *(const float2*)(bias + col);
#pragma unroll
        for (int mi = 0; mi < 2; mi++) {
            int r0 = row0 + wm + mi * 16 + g;
            float o00 = c[mi][ni][0] + bv.x;
            float o01 = c[mi][ni][1] + bv.y;
            float o10 = c[mi][ni][2] + bv.x;
            float o11 = c[mi][ni][3] + bv.y;
            if (conv_out) {
                o00 = __uint_as_float(f2tf(o00));
                o01 = __uint_as_float(f2tf(o01));
                o10 = __uint_as_float(f2tf(o10));
                o11 = __uint_as_float(f2tf(o11));
            }
            *(float2*)(C + (size_t)r0 * N + col) = make_float2(o00, o01);
            *(float2*)(C + (size_t)(r0 + 8) * N + col) = make_float2(o10, o11);
        }
    }
}

// ---------------------------------------------------------------------------
// Flash attention. Block = (b,h,128 Q rows), 128 thr, 3 CTAs/SM (71.7KB smem,
// reg cap 170). Q fragments in registers; K/V cp.async double-buffered; P via
// register shuffles. Reads fused QKV rows (stride 2304); Q pre-scaled.
// ---------------------------------------------------------------------------
#define QSTR 68
#define KSTR 68
#define VSTR 72
#define KWORDS (64 * KSTR)             // 4352
#define VWORDS (64 * VSTR)             // 4608
#define STG    (KWORDS + VWORDS)       // 8960 words per stage
#define ATTN_SMEM (2 * STG * 4)        // 71680 B

__global__ __launch_bounds__(128, 3) void attn_tf32(
    const float* __restrict__ QKV, float* __restrict__ O)
{
    unsigned* smem = dynsmem;
    const uint32_t sbase = (uint32_t)__cvta_generic_to_shared(smem);

    const int tid  = threadIdx.x;
    const int lane = tid & 31;
    const int w    = tid >> 5;
    const int g    = lane >> 2;
    const int t    = lane & 3;
    const int qt   = (gridDim.x - 1) - blockIdx.x;   // big tiles first
    const int h    = blockIdx.y;
    const int b    = blockIdx.z;

    const float* Qptr = QKV + ((size_t)(b * SEQ + qt * 128)) * QKVS + h * HDIM;

#pragma unroll
    for (int i = 0; i < 16; i++) {
        int id = tid + 128 * i, r = id >> 4, cc = id & 15;
        cp16(sbase + (uint32_t)(r * QSTR + cc * 4) * 4, Qptr + (size_t)r * QKVS + cc * 4);
    }
    CP_COMMIT();
    CP_WAIT0();
    __syncthreads();

    unsigned aq[8][2][4];
#pragma unroll
    for (int kp = 0; kp < 8; kp++)
#pragma unroll
        for (int mi = 0; mi < 2; mi++) {
            int r0 = (w * 32 + mi * 16 + g) * QSTR + kp * 8 + t;
            int r1 = r0 + 8 * QSTR;
            aq[kp][mi][0] = smem[r0];
            aq[kp][mi][1] = smem[r1];
            aq[kp][mi][2] = smem[r0 + 4];
            aq[kp][mi][3] = smem[r1 + 4];
        }
    __syncthreads();

    auto load_kv = [&](int kt, int buf) {
        const float* kvb = QKV + ((size_t)(b * SEQ + kt * 64)) * QKVS + h * HDIM;
#pragma unroll
        for (int i = 0; i < 8; i++) {
            int id = tid + 128 * i, r = id >> 4, cc = id & 15;
            cp16(sbase + (uint32_t)(buf * STG + r * KSTR + cc * 4) * 4,
                 kvb + DMODEL + (size_t)r * QKVS + cc * 4);           // K slice
            cp16(sbase + (uint32_t)(buf * STG + KWORDS + r * VSTR + cc * 4) * 4,
                 kvb + 2 * DMODEL + (size_t)r * QKVS + cc * 4);       // V slice
        }
    };
    load_kv(0, 0);
    CP_COMMIT();

    float co[2][8][4];
#pragma unroll
    for (int mi = 0; mi < 2; mi++)
#pragma unroll
        for (int ni = 0; ni < 8; ni++)
#pragma unroll
            for (int r = 0; r < 4; r++) co[mi][ni][r] = 0.0f;
    float mA[2] = {-1e30f, -1e30f}, mB[2] = {-1e30f, -1e30f};
    float lA[2] = {0.0f, 0.0f},     lB[2] = {0.0f, 0.0f};

    const int ntiles = 2 * qt + 2;
    const int srcA = (lane & ~3) | (t >> 1);
    const int srcB = srcA + 2;
    const bool hi = (t & 1);

    for (int kt = 0; kt < ntiles; kt++) {
        CP_WAIT0();
        __syncthreads();
        if (kt + 1 < ntiles) {
            load_kv(kt + 1, (kt + 1) & 1);
            CP_COMMIT();
        }
        const unsigned* Kb = smem + (kt & 1) * STG;
        const unsigned* Vb = Kb + KWORDS;

        float cs[2][8][4];
#pragma unroll
        for (int mi = 0; mi < 2; mi++)
#pragma unroll
            for (int ni = 0; ni < 8; ni++)
#pragma unroll
                for (int r = 0; r < 4; r++) cs[mi][ni][r] = 0.0f;
#pragma unroll
        for (int kp = 0; kp < 8; kp++) {
#pragma unroll
            for (int ni = 0; ni < 8; ni++) {
                unsigned bf[2];
                int rr = (ni * 8 + g) * KSTR + kp * 8 + t;
                bf[0] = Kb[rr];
                bf[1] = Kb[rr + 4];
                mma8(cs[0][ni], aq[kp][0], bf);
                mma8(cs[1][ni], aq[kp][1], bf);
            }
        }

        if (kt >= 2 * qt) {
            const int cb = kt * 64 + 2 * t;
            const int rb = qt * 128 + w * 32 + g;
#pragma unroll
            for (int mi = 0; mi < 2; mi++) {
                int r0 = rb + mi * 16;
#pragma unroll
                for (int ni = 0; ni < 8; ni++) {
                    int col = cb + ni * 8;
                    if (col > r0)         cs[mi][ni][0] = -1e30f;
                    if (col + 1 > r0)     cs[mi][ni][1] = -1e30f;
                    if (col > r0 + 8)     cs[mi][ni][2] = -1e30f;
                    if (col + 1 > r0 + 8) cs[mi][ni][3] = -1e30f;
                }
            }
        }

#pragma unroll
        for (int mi = 0; mi < 2; mi++) {
            float tm0 = -1e30f, tm1 = -1e30f;
#pragma unroll
            for (int ni = 0; ni < 8; ni++) {
                tm0 = fmaxf(tm0, fmaxf(cs[mi][ni][0], cs[mi][ni][1]));
                tm1 = fmaxf(tm1, fmaxf(cs[mi][ni][2], cs[mi][ni][3]));
            }
            tm0 = fmaxf(tm0, __shfl_xor_sync(0xffffffffu, tm0, 1));
            tm0 = fmaxf(tm0, __shfl_xor_sync(0xffffffffu, tm0, 2));
            tm1 = fmaxf(tm1, __shfl_xor_sync(0xffffffffu, tm1, 1));
            tm1 = fmaxf(tm1, __shfl_xor_sync(0xffffffffu, tm1, 2));

            float mn0 = fmaxf(mA[mi], tm0), mn1 = fmaxf(mB[mi], tm1);
            float al0 = ex2f(mA[mi] - mn0), al1 = ex2f(mB[mi] - mn1);
            float s0 = 0.0f, s1 = 0.0f;
#pragma unroll
            for (int ni = 0; ni < 8; ni++) {
                float p0 = ex2f(cs[mi][ni][0] - mn0); s0 += p0;
                float p1 = ex2f(cs[mi][ni][1] - mn0); s0 += p1;
                float p2 = ex2f(cs[mi][ni][2] - mn1); s1 += p2;
                float p3 = ex2f(cs[mi][ni][3] - mn1); s1 += p3;
                cs[mi][ni][0] = __uint_as_float(f2tf(p0));
                cs[mi][ni][1] = __uint_as_float(f2tf(p1));
                cs[mi][ni][2] = __uint_as_float(f2tf(p2));
                cs[mi][ni][3] = __uint_as_float(f2tf(p3));
            }
            s0 += __shfl_xor_sync(0xffffffffu, s0, 1);
            s0 += __shfl_xor_sync(0xffffffffu, s0, 2);
            s1 += __shfl_xor_sync(0xffffffffu, s1, 1);
            s1 += __shfl_xor_sync(0xffffffffu, s1, 2);
            lA[mi] = lA[mi] * al0 + s0;
            lB[mi] = lB[mi] * al1 + s1;
            mA[mi] = mn0; mB[mi] = mn1;
#pragma unroll
            for (int ni = 0; ni < 8; ni++) {
                co[mi][ni][0] *= al0; co[mi][ni][1] *= al0;
                co[mi][ni][2] *= al1; co[mi][ni][3] *= al1;
            }
        }

#pragma unroll
        for (int kp = 0; kp < 8; kp++) {
            unsigned ap[2][4];
#pragma unroll
            for (int mi = 0; mi < 2; mi++) {
                float x0 = __shfl_sync(0xffffffffu, cs[mi][kp][0], srcA);
                float x1 = __shfl_sync(0xffffffffu, cs[mi][kp][1], srcA);
                float y0 = __shfl_sync(0xffffffffu, cs[mi][kp][2], srcA);
                float y1 = __shfl_sync(0xffffffffu, cs[mi][kp][3], srcA);
                float z0 = __shfl_sync(0xffffffffu, cs[mi][kp][0], srcB);
                float z1 = __shfl_sync(0xffffffffu, cs[mi][kp][1], srcB);
                float u0 = __shfl_sync(0xffffffffu, cs[mi][kp][2], srcB);
                float u1 = __shfl_sync(0xffffffffu, cs[mi][kp][3], srcB);
                ap[mi][0] = __float_as_uint(hi ? x1 : x0);
                ap[mi][1] = __float_as_uint(hi ? y1 : y0);
                ap[mi][2] = __float_as_uint(hi ? z1 : z0);
                ap[mi][3] = __float_as_uint(hi ? u1 : u0);
            }
#pragma unroll
            for (int ni = 0; ni < 8; ni++) {
                unsigned bf[2];
                bf[0] = Vb[(kp * 8 + t) * VSTR + ni * 8 + g];
                bf[1] = Vb[(kp * 8 + t + 4) * VSTR + ni * 8 + g];
                mma8(co[0][ni], ap[0], bf);
                mma8(co[1][ni], ap[1], bf);
            }
        }
    }

#pragma unroll
    for (int mi = 0; mi < 2; mi++) {
        const float i0 = 1.0f / lA[mi], i1 = 1.0f / lB[mi];
        size_t rbase = ((size_t)(b * SEQ + qt * 128 + w * 32 + mi * 16 + g)) * DMODEL + h * HDIM;
#pragma unroll
        for (int ni = 0; ni < 8; ni++) {
            size_t r0 = rbase + ni * 8 + 2 * t;
            *(float2*)(O + r0) = make_float2(
                __uint_as_float(f2tf(co[mi][ni][0] * i0)),
                __uint_as_float(f2tf(co[mi][ni][1] * i0)));
            *(float2*)(O + r0 + (size_t)8 * DMODEL) = make_float2(
                __uint_as_float(f2tf(co[mi][ni][2] * i1)),
                __uint_as_float(f2tf(co[mi][ni][3] * i1)));
        }
    }
}

// ---------------------------------------------------------------------------
extern "C" void kernel_launch(void* const* d_in, const int* in_sizes, int n_in,
                              void* d_out, int out_size)
{
    (void)in_sizes; (void)n_in; (void)out_size;
    const float* x  = (const float*)d_in[0];
    const float* wq = (const float*)d_in[1];
    const float* wk = (const float*)d_in[2];
    const float* wv = (const float*)d_in[3];
    const float* wo = (const float*)d_in[4];
    const float* bo = (const float*)d_in[5];
    float* out = (float*)d_out;

    float *xt, *wt, *qkv, *cp;
    cudaGetSymbolAddress((void**)&xt, g_xt);
    cudaGetSymbolAddress((void**)&wt, g_wt);
    cudaGetSymbolAddress((void**)&qkv, g_qkv);
    cudaGetSymbolAddress((void**)&cp, g_ctx);

    static bool attr_done = false;
    if (!attr_done) {
        cudaFuncSetAttribute(gemm_tf32, cudaFuncAttributeMaxDynamicSharedMemorySize, GEMM_SMEM);
        cudaFuncSetAttribute(attn_tf32, cudaFuncAttributeMaxDynamicSharedMemorySize, ATTN_SMEM);
        attr_done = true;
    }

    const float qscale = 0.125f * 1.4426950408889634f;  // 1/sqrt(64) * log2(e)

    // prep: tf32-round x; pack weights (wq scaled, wq/wk/wv interleaved)
    const int NX4 = MTOT * DMODEL / 4;
    const int NW4 = DMODEL * DMODEL / 4;
    prep_tf32<<<(NX4 + 255) / 256, 256>>>(x, xt, NX4);
    dim3 wprep_grid((NW4 + 255) / 256, 4);
    prep_tf32_w<<<wprep_grid, 256>>>(wq, wk, wv, wo, wt, NW4, qscale);

    // fused QKV GEMM: [8192,768] @ [768,2304]
    dim3 qkv_grid(QKVS / TBN, MTOT / TBM);      // (36, 64)
    gemm_tf32<<<qkv_grid, 128, GEMM_SMEM>>>(xt, wt, nullptr, qkv,
                                            MTOT, QKVS, DMODEL, 1);

    dim3 attn_grid(SEQ / 128, NHEADS, BB);      // (32, 12, 2)
    attn_tf32<<<attn_grid, 128, ATTN_SMEM>>>(qkv, cp);

    dim3 out_grid(DMODEL / TBN, MTOT / TBM);    // (12, 64)
    gemm_tf32<<<out_grid, 128, GEMM_SMEM>>>(cp, wt + 3 * DMODEL * DMODEL, bo, out,
                                            MTOT, DMODEL, DMODEL, 0);
}